// round 16
// baseline (speedup 1.0000x reference)
#include <cuda_runtime.h>

#define BB 64
#define CC 3
#define RR 64
#define CL 64
#define EE 64
#define HH 32
#define LL 3
#define VV 258
#define GG 96   // 3*H

typedef unsigned long long u64;

// ---------------- scratch (device globals; no allocation) ----------------
__device__ float g_giemb[CC * VV * GG];                   // [c][v][g] = Wih0[:, :64] @ embed
__device__ float g_wpk[CC * 288 * 96];                    // (for qpre) wi/wh/wq rows per gate
__device__ float g_bpk[CC * 288 * 4];                     // (for qpre) bi, bh, pv
__device__ __align__(16) float g_wpk2[CC * 3 * 32 * 208]; // per-(c,l,u): wiR,wiZ,wiN,whR,whZ,whN[32] + biases + pad
__device__ float g_hid[(size_t)BB * CC * RR * CL * HH];   // all hidden outputs (~100 MB)
__device__ float g_qpre[(size_t)CC * BB * RR * CL * GG];  // hoisted l0 input terms (~302 MB)

// ---------------- helpers ----------------
#define FMA2(acc, a, b) asm("fma.rn.f32x2 %0, %1, %2, %0;" : "+l"(acc) : "l"(a), "l"(b))

__device__ __forceinline__ float sum2p(u64 a, u64 b) {
    u64 s;
    asm("add.rn.f32x2 %0, %1, %2;" : "=l"(s) : "l"(a), "l"(b));
    float lo = __uint_as_float((unsigned)(s & 0xffffffffull));
    float hi = __uint_as_float((unsigned)(s >> 32));
    return lo + hi;
}
__device__ __forceinline__ void cpa16(void* dst, const void* src) {
    unsigned sd = (unsigned)__cvta_generic_to_shared(dst);
    asm volatile("cp.async.ca.shared.global [%0], [%1], 16;" :: "r"(sd), "l"(src) : "memory");
}
__device__ __forceinline__ float sigm_a(float x) {
    float t;
    asm("tanh.approx.f32 %0, %1;" : "=f"(t) : "f"(0.5f * x));
    return fmaf(0.5f, t, 0.5f);
}
__device__ __forceinline__ float tanh_a(float x) {
    float t;
    asm("tanh.approx.f32 %0, %1;" : "=f"(t) : "f"(x));
    return t;
}

// ---------------- dynamic shared layout ----------------
// h buffers double-buffered by step parity (every consumed h is exactly one step old).
// qx TRIPLE-buffered: read s%3, prefetch writes (s+2)%3 — never collides with the
// buffer being read this step (s%3) or next step ((s+1)%3). This removes the race
// that killed R15 without reintroducing a second barrier.
struct SmemT {
    float h0[2][RR][HH];       // layer-0 hidden
    float h1[2][RR][HH];       // layer-1 hidden
    float h2[2][RR + 1][HH];   // layer-2 hidden, +1 row offset; [.][0] = zeros (row -1)
    float qx[3][32][GG];       // hoisted l0 input terms, triple-buffered by step mod 3
};

// ---------------- precompute kernels ----------------
__global__ void prep_giemb(const float* __restrict__ Wih0, const float* __restrict__ embed) {
    int idx = blockIdx.x * blockDim.x + threadIdx.x;
    if (idx >= CC * VV * GG) return;
    int c = idx / (VV * GG);
    int rem = idx % (VV * GG);
    int v = rem / GG;
    int g = rem % GG;
    const float* wr = Wih0 + (c * GG + g) * (EE + 1);
    const float* em = embed + (c * VV + v) * EE;
    float acc = 0.f;
#pragma unroll
    for (int e = 0; e < EE; e++) acc += wr[e] * em[e];
    g_giemb[idx] = acc;
}

// (for qpre) per (c, t in [0,288)): l = t/96, g = t%96; [64:96) holds wq (Wih0 @ W_ad)
__global__ void prep_wpk2(const float* __restrict__ Wih0, const float* __restrict__ Wih_rest,
                          const float* __restrict__ Whh, const float* __restrict__ W_h2e,
                          const float* __restrict__ W_ad) {
    int idx = blockIdx.x * blockDim.x + threadIdx.x;
    if (idx >= CC * 288 * 96) return;
    int c = idx / (288 * 96);
    int rem = idx % (288 * 96);
    int t = rem / 96;
    int j = rem % 96;
    int s = j / 32;
    int k = j % 32;
    int l = t / 96;
    int g = t % 96;
    float val = 0.f;
    if (s == 0) {
        if (l == 0) {
            const float* wr = Wih0 + (c * GG + g) * (EE + 1);
            for (int e = 0; e <= EE; e++)
                val += wr[e] * W_h2e[(c * (EE + 1) + e) * HH + k];
        } else {
            val = Wih_rest[((c * (LL - 1) + (l - 1)) * GG + g) * HH + k];
        }
    } else if (s == 1) {
        val = Whh[((c * LL + l) * GG + g) * HH + k];
    } else {
        if (l == 0 && c > 0) {
            const float* wr = Wih0 + (c * GG + g) * (EE + 1);
            for (int e = 0; e <= EE; e++)
                val += wr[e] * W_ad[((c - 1) * (EE + 1) + e) * HH + k];
        }
    }
    g_wpk[idx] = val;
}

__global__ void prep_bpk2(const float* __restrict__ Wih0, const float* __restrict__ bih,
                          const float* __restrict__ bhh, const float* __restrict__ b_h2e,
                          const float* __restrict__ b_ad) {
    int idx = blockIdx.x * blockDim.x + threadIdx.x;
    if (idx >= CC * 288) return;
    int c = idx / 288;
    int t = idx % 288;
    int l = t / 96;
    int g = t % 96;
    float bi, bh, pv;
    if (l == 0) {
        bi = bih[(c * LL + 0) * GG + g];
        const float* wr = Wih0 + (c * GG + g) * (EE + 1);
        for (int e = 0; e <= EE; e++) {
            float bb = b_h2e[c * (EE + 1) + e];
            if (c > 0) bb += b_ad[(c - 1) * (EE + 1) + e];
            bi += wr[e] * bb;
        }
        pv = Wih0[(c * GG + g) * (EE + 1) + EE];
    } else {
        bi = bih[(c * LL + l) * GG + g];
        pv = 0.f;
    }
    bh = bhh[(c * LL + l) * GG + g];
    g_bpk[idx * 4 + 0] = bi;
    g_bpk[idx * 4 + 1] = bh;
    g_bpk[idx * 4 + 2] = pv;
    g_bpk[idx * 4 + 3] = 0.f;
}

// Fused per-unit weight pack: per (c, l, u): 6 arrays of 32 (wiR,wiZ,wiN,whR,whZ,whN),
// then biases [192..198): biR,biZ,biN (0 for l==0, folded into qpre), bhR,bhZ,bhN.
__global__ void prep_wpk4(const float* __restrict__ Wih0, const float* __restrict__ Wih_rest,
                          const float* __restrict__ Whh, const float* __restrict__ W_h2e,
                          const float* __restrict__ bih, const float* __restrict__ bhh) {
    int idx = blockIdx.x * blockDim.x + threadIdx.x;
    if (idx >= CC * 3 * 32 * 208) return;
    int c = idx / (3 * 32 * 208);
    int rem = idx % (3 * 32 * 208);
    int lu = rem / 208;
    int j = rem % 208;
    int l = lu / 32;
    int u = lu % 32;
    float val = 0.f;
    if (j < 192) {
        int arr = j / 32, k = j % 32;
        int side = arr / 3;         // 0 = wi, 1 = wh
        int g = u + (arr % 3) * 32; // gate index: r, z, n
        if (side == 0) {
            if (l == 0) {
                const float* wr = Wih0 + (c * GG + g) * (EE + 1);
                for (int e = 0; e <= EE; e++)
                    val += wr[e] * W_h2e[(c * (EE + 1) + e) * HH + k];
            } else {
                val = Wih_rest[((c * (LL - 1) + (l - 1)) * GG + g) * HH + k];
            }
        } else {
            val = Whh[((c * LL + l) * GG + g) * HH + k];
        }
    } else if (j < 198) {
        int i = j - 192;
        if (i < 3) val = (l == 0) ? 0.f : bih[(c * LL + l) * GG + (u + i * 32)];
        else val = bhh[(c * LL + l) * GG + (u + (i - 3) * 32)];
    }
    g_wpk2[idx] = val;
}

// ---------------- qpre: full layer-0 input-side hoist (R13, proven) ----------------
__global__ void __launch_bounds__(96, 8) qpre_kernel(int c, const int* __restrict__ x) {
    __shared__ __align__(16) float sh[32][32];
    __shared__ int sx[32];
    const int g = threadIdx.x;
    const size_t pos0 = (size_t)blockIdx.x * 32;
    const int b = (int)(pos0 >> 12);
    const int rt0 = (int)(pos0 & 4095);
    const int r = rt0 >> 6;
    const float posr = (float)r * (1.f / 32.f) - 1.f;

    ulonglong2 wq[8];
    if (c > 0) {
        const ulonglong2* wsrc =
            reinterpret_cast<const ulonglong2*>(g_wpk + ((size_t)(c * 288 + g)) * 96 + 64);
#pragma unroll
        for (int i = 0; i < 8; i++) wq[i] = wsrc[i];
        const float4* hsrc = reinterpret_cast<const float4*>(
            g_hid + ((size_t)(b * CC + c - 1) * (RR * CL) + rt0) * HH);
        float4* shd = reinterpret_cast<float4*>(&sh[0][0]);
        for (int i = g; i < 256; i += 96) shd[i] = hsrc[i];
    }
    if (g < 32) sx[g] = x[((size_t)(b * CC + c) * (RR * CL)) + rt0 + g];
    __syncthreads();

    const float bi = g_bpk[(c * 288 + g) * 4 + 0];
    const float pv = g_bpk[(c * 288 + g) * 4 + 2];
    const float badd = fmaf(pv, posr, bi);

    const float* giC = g_giemb + (size_t)c * VV * GG;
    float* outp = g_qpre + ((size_t)c * (BB * RR * CL) + pos0) * GG + g;
#pragma unroll 4
    for (int p = 0; p < 32; p++) {
        float val = __ldg(giC + (size_t)sx[p] * GG + g) + badd;
        if (c > 0) {
            u64 A0 = 0, A1 = 0;
            const ulonglong2* hv = reinterpret_cast<const ulonglong2*>(&sh[p][0]);
#pragma unroll
            for (int i = 0; i < 8; i++) {
                FMA2(A0, wq[i].x, hv[i].x);
                FMA2(A1, wq[i].y, hv[i].y);
            }
            val += sum2p(A0, A1);
        }
        outp[(size_t)p * GG] = val;
    }
}

// ---------------- wavefront RNN kernel: fused gate+cell, one barrier/step ----------------
// Schedule: layer l of cell (r,t) at step s = 3r + t + l. Thread u of warp (l, sub=r%3)
// computes the FULL GRU unit u: 6 dots (3 gates x 2 sides) from 2 vector loads, then
// activation and h update inline. h double-buffered by step parity; qx triple-buffered
// (read s%3, prefetch (s+2)%3). cp.async: issue(s+2) -> commit -> wait 1 -> bar.
__global__ void __launch_bounds__(288, 1) rnn_kernel(int c) {
    extern __shared__ __align__(16) char smem_raw[];
    SmemT* sm = reinterpret_cast<SmemT*>(smem_raw);

    const int b = blockIdx.x;
    const int tid = threadIdx.x;
    const int l = tid / 96;            // layer group (warp-uniform)
    const int sub = (tid % 96) >> 5;   // row-parity warp (r % 3 == sub)
    const int u = tid & 31;            // hidden unit

    // per-thread fused weights: 48 ulonglong2 = 96 regs
    const ulonglong2* wsrc =
        reinterpret_cast<const ulonglong2*>(g_wpk2 + ((size_t)((c * 3 + l) * 32 + u)) * 208);
    ulonglong2 wiR[8], wiZ[8], wiN[8], whR[8], whZ[8], whN[8];
#pragma unroll
    for (int i = 0; i < 8; i++) wiR[i] = wsrc[i];
#pragma unroll
    for (int i = 0; i < 8; i++) wiZ[i] = wsrc[8 + i];
#pragma unroll
    for (int i = 0; i < 8; i++) wiN[i] = wsrc[16 + i];
#pragma unroll
    for (int i = 0; i < 8; i++) whR[i] = wsrc[24 + i];
#pragma unroll
    for (int i = 0; i < 8; i++) whZ[i] = wsrc[32 + i];
#pragma unroll
    for (int i = 0; i < 8; i++) whN[i] = wsrc[40 + i];
    const float* bsrc = g_wpk2 + ((size_t)((c * 3 + l) * 32 + u)) * 208 + 192;
    const float biR = bsrc[0], biZ = bsrc[1], biN = bsrc[2];
    const float bhR = bsrc[3], bhZ = bsrc[4], bhN = bsrc[5];

    const float* qpreC = g_qpre + ((size_t)c * BB + b) * (RR * CL) * GG;
    float* hidG = g_hid + (size_t)(b * CC + c) * (RR * CL * HH);

    // zero all hidden-state buffers (h0,h1,h2 contiguous; both parities)
    for (int i = tid; i < (2 * RR + 2 * RR + 2 * (RR + 1)) * HH; i += 288)
        (&sm->h0[0][0][0])[i] = 0.f;

    // qx prefetch: fill buf (m2 % 3) for layer-0 cells on line 3r+t = m2
    auto issue_qx = [&](int m2) {
        if (m2 > 252) return;
        int rlo2 = m2 > 61 ? (m2 - 61) / 3 : 0;
        int rhi2 = min(63, m2 / 3);
        int nch = (rhi2 - rlo2 + 1) * 24;  // 24 x 16B chunks per cell (96 floats)
        for (int id = tid; id < nch; id += 288) {
            int ce = id / 24, sb2 = id % 24;
            int r = rlo2 + ce, t = m2 - 3 * r;
            cpa16(&sm->qx[m2 % 3][r & 31][sb2 * 4],
                  qpreC + ((size_t)(r * CL + t) * GG + sb2 * 4));
        }
    };

    issue_qx(0);
    asm volatile("cp.async.commit_group;" ::: "memory");
    issue_qx(1);
    asm volatile("cp.async.commit_group;" ::: "memory");
    asm volatile("cp.async.wait_group 1;" ::: "memory");  // qx(0) landed (this thread)
    __syncthreads();                                       // h zero + qx(0) published

    for (int s = 0; s < 255; s++) {
        const int m = s - l;  // warp-uniform diagonal for this layer group
        const bool act = (m >= 0) && (m <= 252);
        if (act) {
            int rlo = m > 61 ? (m - 61) / 3 : 0;
            int rhi = min(63, m / 3);
            const int rb = (s + 1) & 1;  // read parity = (s-1)&1
            const int wb = s & 1;        // write parity
            const int qb = s % 3;        // qx read buffer (l==0 only)
            int r = rlo + (((sub - rlo) % 3) + 3) % 3;  // first row of this parity warp
            for (; r <= rhi; r += 3) {
                const int t = m - 3 * r;
                const float* hvp;
                const float* ivp;
                float* wvp;
                if (l == 0) {
                    hvp = &sm->h0[rb][r][0];
                    ivp = &sm->h2[rb][r][0];    // prev row's h2 (+1 offset array)
                    wvp = &sm->h0[wb][r][0];
                } else if (l == 1) {
                    hvp = &sm->h1[rb][r][0];
                    ivp = &sm->h0[rb][r][0];
                    wvp = &sm->h1[wb][r][0];
                } else {
                    hvp = &sm->h2[rb][r + 1][0];
                    ivp = &sm->h1[rb][r][0];
                    wvp = &sm->h2[wb][r + 1][0];
                }
                const ulonglong2* hv = reinterpret_cast<const ulonglong2*>(hvp);
                const ulonglong2* iv = reinterpret_cast<const ulonglong2*>(ivp);

                u64 AR0 = 0, AR1 = 0, AZ0 = 0, AZ1 = 0, AN0 = 0, AN1 = 0;
                u64 BR0 = 0, BR1 = 0, BZ0 = 0, BZ1 = 0, BN0 = 0, BN1 = 0;
#pragma unroll
                for (int i = 0; i < 8; i++) {
                    ulonglong2 xx = hv[i];
                    ulonglong2 yy = iv[i];
                    FMA2(AR0, whR[i].x, xx.x); FMA2(AR1, whR[i].y, xx.y);
                    FMA2(AZ0, whZ[i].x, xx.x); FMA2(AZ1, whZ[i].y, xx.y);
                    FMA2(AN0, whN[i].x, xx.x); FMA2(AN1, whN[i].y, xx.y);
                    FMA2(BR0, wiR[i].x, yy.x); FMA2(BR1, wiR[i].y, yy.y);
                    FMA2(BZ0, wiZ[i].x, yy.x); FMA2(BZ1, wiZ[i].y, yy.y);
                    FMA2(BN0, wiN[i].x, yy.x); FMA2(BN1, wiN[i].y, yy.y);
                }
                float qr, qz, qn;
                if (l == 0) {  // l0 input-side constants live in qx (bi + pv*pos folded)
                    const int slot = r & 31;
                    qr = sm->qx[qb][slot][u];
                    qz = sm->qx[qb][slot][32 + u];
                    qn = sm->qx[qb][slot][64 + u];
                } else {
                    qr = biR; qz = biZ; qn = biN;
                }
                float gr = sum2p(BR0, BR1) + qr + sum2p(AR0, AR1) + bhR;
                float gz = sum2p(BZ0, BZ1) + qz + sum2p(AZ0, AZ1) + bhZ;
                float hnv = sum2p(AN0, AN1) + bhN;
                float inv = sum2p(BN0, BN1) + qn;
                float rg = sigm_a(gr);
                float zg = sigm_a(gz);
                float ng = tanh_a(fmaf(rg, hnv, inv));
                float hold = hvp[u];
                float hn = fmaf(zg, hold - ng, ng);
                wvp[u] = hn;
                if (l == 2) hidG[(size_t)(r * CL + t) * HH + u] = hn;
            }
        }
        issue_qx(s + 2);  // writes buf (s+2)%3: disjoint from read bufs s%3 and (s+1)%3
        asm volatile("cp.async.commit_group;" ::: "memory");
        asm volatile("cp.async.wait_group 1;" ::: "memory");  // qx(s+1) landed (this thread)
        __syncthreads();                                       // publish h writes + qx(s+1)
    }
}

// ---------------- output projection with packed f32x2 FMA ----------------
__global__ void __launch_bounds__(256, 2) proj_kernel(const float* __restrict__ Wout,
                                                      const float* __restrict__ bout,
                                                      float* __restrict__ out) {
    __shared__ float Ws[32][264];  // Ws[k][v]
    __shared__ float hs[32][72];   // hs[k][p]
    __shared__ float bs[264];

    const int tid = threadIdx.x;
    const size_t p0 = (size_t)blockIdx.x * 64;

    for (int i = tid; i < VV * HH; i += 256) {
        int v = i >> 5, k = i & 31;
        Ws[k][v] = Wout[i];
    }
    if (tid < 256) bs[tid] = (tid < VV) ? bout[tid] : 0.f;
    if (tid < 2) bs[256 + tid] = bout[256 + tid];
    if (tid < 6) bs[258 + tid] = 0.f;
    {
        const float* hsrc = g_hid + p0 * HH;
        for (int i = tid; i < 64 * HH; i += 256) {
            int p = i >> 5, k = i & 31;
            hs[k][p] = hsrc[i];
        }
    }
    __syncthreads();

    const int tv = tid & 31;
    const int tp = tid >> 5;
    const int vb = tv * 8, pb = tp * 8;

    u64 acc[8][4];
#pragma unroll
    for (int pi = 0; pi < 8; pi++)
#pragma unroll
        for (int j = 0; j < 4; j++) acc[pi][j] = 0ull;

#pragma unroll 2
    for (int k = 0; k < 32; k++) {
        ulonglong2 w0 = *reinterpret_cast<const ulonglong2*>(&Ws[k][vb]);
        ulonglong2 w1 = *reinterpret_cast<const ulonglong2*>(&Ws[k][vb + 4]);
        float4 ha = *reinterpret_cast<const float4*>(&hs[k][pb]);
        float4 hb = *reinterpret_cast<const float4*>(&hs[k][pb + 4]);
        float hv[8] = {ha.x, ha.y, ha.z, ha.w, hb.x, hb.y, hb.z, hb.w};
#pragma unroll
        for (int pi = 0; pi < 8; pi++) {
            u64 hp;
            asm("mov.b64 %0, {%1, %1};" : "=l"(hp) : "f"(hv[pi]));
            FMA2(acc[pi][0], hp, w0.x);
            FMA2(acc[pi][1], hp, w0.y);
            FMA2(acc[pi][2], hp, w1.x);
            FMA2(acc[pi][3], hp, w1.y);
        }
    }

    ulonglong2 bz0 = *reinterpret_cast<const ulonglong2*>(&bs[vb]);
    ulonglong2 bz1 = *reinterpret_cast<const ulonglong2*>(&bs[vb + 4]);
    u64 bzv[4] = {bz0.x, bz0.y, bz1.x, bz1.y};

#pragma unroll
    for (int pi = 0; pi < 8; pi++) {
        size_t base = (p0 + pb + pi) * VV + vb;
#pragma unroll
        for (int j = 0; j < 4; j++) {
            u64 o;
            asm("add.rn.f32x2 %0, %1, %2;" : "=l"(o) : "l"(acc[pi][j]), "l"(bzv[j]));
            *reinterpret_cast<u64*>(&out[base + 2 * j]) = o;
        }
    }

    // tail columns v = 256, 257
    if (tid < 128) {
        int p = tid >> 1;
        int v = 256 + (tid & 1);
        float a = bs[v];
#pragma unroll
        for (int k = 0; k < 32; k++) a = fmaf(hs[k][p], Ws[k][v], a);
        out[(p0 + p) * VV + v] = a;
    }
}

// ---------------- launcher ----------------
extern "C" void kernel_launch(void* const* d_in, const int* in_sizes, int n_in,
                              void* d_out, int out_size) {
    const int* x = (const int*)d_in[0];
    const float* embed = (const float*)d_in[1];
    const float* Wih0 = (const float*)d_in[2];
    const float* Wih_rest = (const float*)d_in[3];
    const float* Whh = (const float*)d_in[4];
    const float* bih = (const float*)d_in[5];
    const float* bhh = (const float*)d_in[6];
    const float* W_h2e = (const float*)d_in[7];
    const float* b_h2e = (const float*)d_in[8];
    const float* W_ad = (const float*)d_in[9];
    const float* b_ad = (const float*)d_in[10];
    const float* W_out = (const float*)d_in[11];
    const float* b_out = (const float*)d_in[12];
    float* out = (float*)d_out;

    cudaFuncSetAttribute(rnn_kernel, cudaFuncAttributeMaxDynamicSharedMemorySize,
                         (int)sizeof(SmemT));

    prep_giemb<<<(CC * VV * GG + 127) / 128, 128>>>(Wih0, embed);
    prep_wpk2<<<(CC * 288 * 96 + 127) / 128, 128>>>(Wih0, Wih_rest, Whh, W_h2e, W_ad);
    prep_bpk2<<<(CC * 288 + 127) / 128, 128>>>(Wih0, bih, bhh, b_h2e, b_ad);
    prep_wpk4<<<(CC * 3 * 32 * 208 + 127) / 128, 128>>>(Wih0, Wih_rest, Whh, W_h2e, bih, bhh);

    for (int c = 0; c < CC; c++) {
        qpre_kernel<<<(BB * RR * CL) / 32, 96>>>(c, x);
        rnn_kernel<<<BB, 288, sizeof(SmemT)>>>(c);
    }
    proj_kernel<<<(BB * CC * RR * CL) / 64, 256>>>(W_out, b_out, out);
}

// round 17
// speedup vs baseline: 1.8839x; 1.8839x over previous
#include <cuda_runtime.h>

#define BB 64
#define CC 3
#define RR 64
#define CL 64
#define EE 64
#define HH 32
#define LL 3
#define VV 258
#define GG 96   // 3*H

typedef unsigned long long u64;

// ---------------- scratch (device globals; no allocation) ----------------
__device__ float g_giemb[CC * VV * GG];                   // [c][v][g] = Wih0[:, :64] @ embed
__device__ float g_wpk[CC * 288 * 96];                    // per-gate packed rows: wi[32], wh[32], wq[32]
__device__ float g_bpk[CC * 288 * 4];                     // per-gate bias: (bi, bh, pv, 0)
__device__ float g_hid[(size_t)BB * CC * RR * CL * HH];   // all hidden outputs (~100 MB)
__device__ float g_qpre[(size_t)CC * BB * RR * CL * GG];  // hoisted l0 input terms (~302 MB)

// ---------------- helpers ----------------
#define FMA2(acc, a, b) asm("fma.rn.f32x2 %0, %1, %2, %0;" : "+l"(acc) : "l"(a), "l"(b))

__device__ __forceinline__ float sum2p(u64 a, u64 b) {
    u64 s;
    asm("add.rn.f32x2 %0, %1, %2;" : "=l"(s) : "l"(a), "l"(b));
    float lo = __uint_as_float((unsigned)(s & 0xffffffffull));
    float hi = __uint_as_float((unsigned)(s >> 32));
    return lo + hi;
}
__device__ __forceinline__ void cpa16(void* dst, const void* src) {
    unsigned sd = (unsigned)__cvta_generic_to_shared(dst);
    asm volatile("cp.async.ca.shared.global [%0], [%1], 16;" :: "r"(sd), "l"(src) : "memory");
}
__device__ __forceinline__ float sigm_a(float x) {
    float t;
    asm("tanh.approx.f32 %0, %1;" : "=f"(t) : "f"(0.5f * x));
    return fmaf(0.5f, t, 0.5f);
}
__device__ __forceinline__ float tanh_a(float x) {
    float t;
    asm("tanh.approx.f32 %0, %1;" : "=f"(t) : "f"(x));
    return t;
}

// ---------------- dynamic shared layout (R14, proven) ----------------
struct SmemT {
    float hs0[RR][HH];       // layer-0 hidden per row
    float hs1[RR][HH];       // layer-1 hidden per row
    float hs2[RR + 1][HH];   // layer-2 hidden per row, +1 offset; [0] = zeros (row -1)
    float rz[LL][32][64];    // finished sigma(r), sigma(z) per (layer, slot=r&31)
    float2 n2[LL][32][HH];   // (i_n, h_n) pairs
    float qx[2][32][GG];     // hoisted l0 input terms, double-buffered by step parity
};

// ---------------- precompute kernels (R13, proven) ----------------
__global__ void prep_giemb(const float* __restrict__ Wih0, const float* __restrict__ embed) {
    int idx = blockIdx.x * blockDim.x + threadIdx.x;
    if (idx >= CC * VV * GG) return;
    int c = idx / (VV * GG);
    int rem = idx % (VV * GG);
    int v = rem / GG;
    int g = rem % GG;
    const float* wr = Wih0 + (c * GG + g) * (EE + 1);
    const float* em = embed + (c * VV + v) * EE;
    float acc = 0.f;
#pragma unroll
    for (int e = 0; e < EE; e++) acc += wr[e] * em[e];
    g_giemb[idx] = acc;
}

// Per (c, t in [0,288)): l = t/96, g = t%96. 96 floats:
//   [0:32)  wi : l==0 -> Wfh[g] (Wih0 @ W_h2e); l>=1 -> Wih_rest[c][l-1][g]
//   [32:64) wh : Whh[c][l][g]
//   [64:96) wq : l==0 && c>0 -> Wfad[g] (Wih0 @ W_ad); else 0   (used by qpre kernel)
__global__ void prep_wpk2(const float* __restrict__ Wih0, const float* __restrict__ Wih_rest,
                          const float* __restrict__ Whh, const float* __restrict__ W_h2e,
                          const float* __restrict__ W_ad) {
    int idx = blockIdx.x * blockDim.x + threadIdx.x;
    if (idx >= CC * 288 * 96) return;
    int c = idx / (288 * 96);
    int rem = idx % (288 * 96);
    int t = rem / 96;
    int j = rem % 96;
    int s = j / 32;
    int k = j % 32;
    int l = t / 96;
    int g = t % 96;
    float val = 0.f;
    if (s == 0) {
        if (l == 0) {
            const float* wr = Wih0 + (c * GG + g) * (EE + 1);
            for (int e = 0; e <= EE; e++)
                val += wr[e] * W_h2e[(c * (EE + 1) + e) * HH + k];
        } else {
            val = Wih_rest[((c * (LL - 1) + (l - 1)) * GG + g) * HH + k];
        }
    } else if (s == 1) {
        val = Whh[((c * LL + l) * GG + g) * HH + k];
    } else {
        if (l == 0 && c > 0) {
            const float* wr = Wih0 + (c * GG + g) * (EE + 1);
            for (int e = 0; e <= EE; e++)
                val += wr[e] * W_ad[((c - 1) * (EE + 1) + e) * HH + k];
        }
    }
    g_wpk[idx] = val;
}

__global__ void prep_bpk2(const float* __restrict__ Wih0, const float* __restrict__ bih,
                          const float* __restrict__ bhh, const float* __restrict__ b_h2e,
                          const float* __restrict__ b_ad) {
    int idx = blockIdx.x * blockDim.x + threadIdx.x;
    if (idx >= CC * 288) return;
    int c = idx / 288;
    int t = idx % 288;
    int l = t / 96;
    int g = t % 96;
    float bi, bh, pv;
    if (l == 0) {
        bi = bih[(c * LL + 0) * GG + g];
        const float* wr = Wih0 + (c * GG + g) * (EE + 1);
        for (int e = 0; e <= EE; e++) {
            float bb = b_h2e[c * (EE + 1) + e];
            if (c > 0) bb += b_ad[(c - 1) * (EE + 1) + e];
            bi += wr[e] * bb;
        }
        pv = Wih0[(c * GG + g) * (EE + 1) + EE];
    } else {
        bi = bih[(c * LL + l) * GG + g];
        pv = 0.f;
    }
    bh = bhh[(c * LL + l) * GG + g];
    g_bpk[idx * 4 + 0] = bi;
    g_bpk[idx * 4 + 1] = bh;
    g_bpk[idx * 4 + 2] = pv;
    g_bpk[idx * 4 + 3] = 0.f;
}

// ---------------- qpre: full layer-0 input-side hoist (R13, proven) ----------------
__global__ void __launch_bounds__(96, 8) qpre_kernel(int c, const int* __restrict__ x) {
    __shared__ __align__(16) float sh[32][32];
    __shared__ int sx[32];
    const int g = threadIdx.x;
    const size_t pos0 = (size_t)blockIdx.x * 32;
    const int b = (int)(pos0 >> 12);
    const int rt0 = (int)(pos0 & 4095);
    const int r = rt0 >> 6;
    const float posr = (float)r * (1.f / 32.f) - 1.f;

    ulonglong2 wq[8];
    if (c > 0) {
        const ulonglong2* wsrc =
            reinterpret_cast<const ulonglong2*>(g_wpk + ((size_t)(c * 288 + g)) * 96 + 64);
#pragma unroll
        for (int i = 0; i < 8; i++) wq[i] = wsrc[i];
        const float4* hsrc = reinterpret_cast<const float4*>(
            g_hid + ((size_t)(b * CC + c - 1) * (RR * CL) + rt0) * HH);
        float4* shd = reinterpret_cast<float4*>(&sh[0][0]);
        for (int i = g; i < 256; i += 96) shd[i] = hsrc[i];
    }
    if (g < 32) sx[g] = x[((size_t)(b * CC + c) * (RR * CL)) + rt0 + g];
    __syncthreads();

    const float bi = g_bpk[(c * 288 + g) * 4 + 0];
    const float pv = g_bpk[(c * 288 + g) * 4 + 2];
    const float badd = fmaf(pv, posr, bi);

    const float* giC = g_giemb + (size_t)c * VV * GG;
    float* outp = g_qpre + ((size_t)c * (BB * RR * CL) + pos0) * GG + g;
#pragma unroll 4
    for (int p = 0; p < 32; p++) {
        float val = __ldg(giC + (size_t)sx[p] * GG + g) + badd;
        if (c > 0) {
            u64 A0 = 0, A1 = 0;
            const ulonglong2* hv = reinterpret_cast<const ulonglong2*>(&sh[p][0]);
#pragma unroll
            for (int i = 0; i < 8; i++) {
                FMA2(A0, wq[i].x, hv[i].x);
                FMA2(A1, wq[i].y, hv[i].y);
            }
            val += sum2p(A0, A1);
        }
        outp[(size_t)p * GG] = val;
    }
}

// ---------------- wavefront RNN kernel: 576 threads, cell-split warpsets ----------------
// Schedule: layer l of cell (r,t) at step s = 3r + t + l (R11/R13, proven).
// Layer group = 192 threads = 2 warpsets x 96 gate threads. Warpset p handles diagonal
// cells r = rlo+p, rlo+p+2, ... — sequential work per warp HALVES vs R14 with the same
// total instruction count (no shfl, no extra LDS). Cell phase: 6 warps/group -> 6 cells
// in flight. qx[2] + two barriers per step exactly as R13/R14 (mid barrier separates
// qx reads from the overwriting prefetch).
__global__ void __launch_bounds__(576, 1) rnn_kernel(int c) {
    extern __shared__ __align__(16) char smem_raw[];
    SmemT* sm = reinterpret_cast<SmemT*>(smem_raw);

    const int b = blockIdx.x;
    const int tid = threadIdx.x;
    const int l = tid / 192;             // layer group (warp-uniform)
    const int t192 = tid % 192;
    const int p = t192 / 96;             // cell-parity warpset (warp-uniform)
    const int g = t192 % 96;             // gate
    const int w6 = t192 >> 5;            // warp within group (0..5), for cell phase
    const int u = tid & 31;              // lane = cell-phase unit

    // per-thread packed weights (f32x2 pairs): 64 regs
    const ulonglong2* wv =
        reinterpret_cast<const ulonglong2*>(g_wpk + ((size_t)(c * 288 + l * 96 + g)) * 96);
    ulonglong2 wi[8], wh[8];
#pragma unroll
    for (int i = 0; i < 8; i++) wi[i] = wv[i];
#pragma unroll
    for (int i = 0; i < 8; i++) wh[i] = wv[8 + i];
    const float4 bias = reinterpret_cast<const float4*>(g_bpk)[c * 288 + l * 96 + g];

    const float* qpreC = g_qpre + ((size_t)c * BB + b) * (RR * CL) * GG;
    float* hidG = g_hid + (size_t)(b * CC + c) * (RR * CL * HH);

    // zero hidden states (hs0,hs1,hs2 contiguous)
    for (int i = tid; i < (RR + RR + RR + 1) * HH; i += 576) (&sm->hs0[0][0])[i] = 0.f;

    // qx prefetch: fill buf (m2&1) with qpre for layer-0 cells on line 3r+t = m2
    auto issue_qx = [&](int m2) {
        if (m2 > 252) return;
        int rlo2 = m2 > 61 ? (m2 - 61) / 3 : 0;
        int rhi2 = min(63, m2 / 3);
        int nch = (rhi2 - rlo2 + 1) * 24;  // 24 x 16B chunks per cell (96 floats)
        for (int id = tid; id < nch; id += 576) {
            int ce = id / 24, sb2 = id % 24;
            int r = rlo2 + ce, t = m2 - 3 * r;
            cpa16(&sm->qx[m2 & 1][r & 31][sb2 * 4],
                  qpreC + ((size_t)(r * CL + t) * GG + sb2 * 4));
        }
    };

    issue_qx(0);
    asm volatile("cp.async.commit_group;" ::: "memory");
    issue_qx(1);
    asm volatile("cp.async.commit_group;" ::: "memory");
    asm volatile("cp.async.wait_group 1;" ::: "memory");  // qx(0) landed (this thread)
    __syncthreads();                                       // hs zero + qx(0) published

    for (int s = 0; s < 255; s++) {
        const int m = s - l;  // warp-uniform diagonal for this layer group
        const bool act = (m >= 0) && (m <= 252);
        int rlo = 0, rhi = -1;
        if (act) {
            rlo = m > 61 ? (m - 61) / 3 : 0;
            rhi = min(63, m / 3);
        }

        // ---------- gate phase: warpset p handles cells r = rlo+p, rlo+p+2, ... ----------
        if (act) {
            const float* hbase = (l == 0) ? &sm->hs0[0][0]
                               : (l == 1) ? &sm->hs1[0][0] : &sm->hs2[1][0];
            const float* ibase = (l == 0) ? &sm->hs2[0][0]
                               : (l == 1) ? &sm->hs0[0][0] : &sm->hs1[0][0];
            const int buf = s & 1;
            for (int r = rlo + p; r <= rhi; r += 2) {
                const int slot = r & 31;
                float qv = (l == 0) ? sm->qx[buf][slot][g] : bias.x;
                u64 A0 = 0, A1 = 0, B0 = 0, B1 = 0;
                const ulonglong2* hv = reinterpret_cast<const ulonglong2*>(hbase + r * HH);
                const ulonglong2* iv = reinterpret_cast<const ulonglong2*>(ibase + r * HH);
#pragma unroll
                for (int i = 0; i < 8; i++) {
                    ulonglong2 xa = hv[i], ya = iv[i];
                    FMA2(A0, wh[i].x, xa.x);
                    FMA2(A1, wh[i].y, xa.y);
                    FMA2(B0, wi[i].x, ya.x);
                    FMA2(B1, wi[i].y, ya.y);
                }
                float ah = sum2p(A0, A1) + bias.y;
                float ai = sum2p(B0, B1) + qv;
                if (g < 64) sm->rz[l][slot][g] = sigm_a(ai + ah);
                else sm->n2[l][slot][g - 64] = make_float2(ai, ah);
            }
        }
        __syncthreads();  // separates qx/hs reads from cell writes + qx prefetch

        // ---------- cell phase: 6 warps/group -> cells r = rlo + w6 + 6k ----------
        if (act) {
            for (int r = rlo + w6; r <= rhi; r += 6) {
                int slot = r & 31;
                int t = m - 3 * r;
                float rg = sm->rz[l][slot][u];
                float zg = sm->rz[l][slot][32 + u];
                float2 nn = sm->n2[l][slot][u];
                float ng = tanh_a(fmaf(rg, nn.y, nn.x));
                float* hrow = (l == 0) ? &sm->hs0[r][0]
                            : (l == 1) ? &sm->hs1[r][0] : &sm->hs2[r + 1][0];
                float hold = hrow[u];
                float hn = fmaf(zg, hold - ng, ng);
                hrow[u] = hn;
                if (l == 2) hidG[(size_t)(r * CL + t) * HH + u] = hn;
            }
        }
        issue_qx(s + 2);  // writes buf (s&1): gate-phase reads of it are pre-mid-barrier
        asm volatile("cp.async.commit_group;" ::: "memory");
        asm volatile("cp.async.wait_group 1;" ::: "memory");  // qx(s+1) landed (this thread)
        __syncthreads();                                       // published for step s+1
    }
}

// ---------------- output projection with packed f32x2 FMA (R13, proven) ----------------
__global__ void __launch_bounds__(256, 2) proj_kernel(const float* __restrict__ Wout,
                                                      const float* __restrict__ bout,
                                                      float* __restrict__ out) {
    __shared__ float Ws[32][264];  // Ws[k][v]
    __shared__ float hs[32][72];   // hs[k][p]
    __shared__ float bs[264];

    const int tid = threadIdx.x;
    const size_t p0 = (size_t)blockIdx.x * 64;

    for (int i = tid; i < VV * HH; i += 256) {
        int v = i >> 5, k = i & 31;
        Ws[k][v] = Wout[i];
    }
    if (tid < 256) bs[tid] = (tid < VV) ? bout[tid] : 0.f;
    if (tid < 2) bs[256 + tid] = bout[256 + tid];
    if (tid < 6) bs[258 + tid] = 0.f;
    {
        const float* hsrc = g_hid + p0 * HH;
        for (int i = tid; i < 64 * HH; i += 256) {
            int p = i >> 5, k = i & 31;
            hs[k][p] = hsrc[i];
        }
    }
    __syncthreads();

    const int tv = tid & 31;
    const int tp = tid >> 5;
    const int vb = tv * 8, pb = tp * 8;

    u64 acc[8][4];
#pragma unroll
    for (int pi = 0; pi < 8; pi++)
#pragma unroll
        for (int j = 0; j < 4; j++) acc[pi][j] = 0ull;

#pragma unroll 2
    for (int k = 0; k < 32; k++) {
        ulonglong2 w0 = *reinterpret_cast<const ulonglong2*>(&Ws[k][vb]);
        ulonglong2 w1 = *reinterpret_cast<const ulonglong2*>(&Ws[k][vb + 4]);
        float4 ha = *reinterpret_cast<const float4*>(&hs[k][pb]);
        float4 hb = *reinterpret_cast<const float4*>(&hs[k][pb + 4]);
        float hv[8] = {ha.x, ha.y, ha.z, ha.w, hb.x, hb.y, hb.z, hb.w};
#pragma unroll
        for (int pi = 0; pi < 8; pi++) {
            u64 hp;
            asm("mov.b64 %0, {%1, %1};" : "=l"(hp) : "f"(hv[pi]));
            FMA2(acc[pi][0], hp, w0.x);
            FMA2(acc[pi][1], hp, w0.y);
            FMA2(acc[pi][2], hp, w1.x);
            FMA2(acc[pi][3], hp, w1.y);
        }
    }

    ulonglong2 bz0 = *reinterpret_cast<const ulonglong2*>(&bs[vb]);
    ulonglong2 bz1 = *reinterpret_cast<const ulonglong2*>(&bs[vb + 4]);
    u64 bzv[4] = {bz0.x, bz0.y, bz1.x, bz1.y};

#pragma unroll
    for (int pi = 0; pi < 8; pi++) {
        size_t base = (p0 + pb + pi) * VV + vb;
#pragma unroll
        for (int j = 0; j < 4; j++) {
            u64 o;
            asm("add.rn.f32x2 %0, %1, %2;" : "=l"(o) : "l"(acc[pi][j]), "l"(bzv[j]));
            *reinterpret_cast<u64*>(&out[base + 2 * j]) = o;
        }
    }

    // tail columns v = 256, 257
    if (tid < 128) {
        int p = tid >> 1;
        int v = 256 + (tid & 1);
        float a = bs[v];
#pragma unroll
        for (int k = 0; k < 32; k++) a = fmaf(hs[k][p], Ws[k][v], a);
        out[(p0 + p) * VV + v] = a;
    }
}

// ---------------- launcher ----------------
extern "C" void kernel_launch(void* const* d_in, const int* in_sizes, int n_in,
                              void* d_out, int out_size) {
    const int* x = (const int*)d_in[0];
    const float* embed = (const float*)d_in[1];
    const float* Wih0 = (const float*)d_in[2];
    const float* Wih_rest = (const float*)d_in[3];
    const float* Whh = (const float*)d_in[4];
    const float* bih = (const float*)d_in[5];
    const float* bhh = (const float*)d_in[6];
    const float* W_h2e = (const float*)d_in[7];
    const float* b_h2e = (const float*)d_in[8];
    const float* W_ad = (const float*)d_in[9];
    const float* b_ad = (const float*)d_in[10];
    const float* W_out = (const float*)d_in[11];
    const float* b_out = (const float*)d_in[12];
    float* out = (float*)d_out;

    cudaFuncSetAttribute(rnn_kernel, cudaFuncAttributeMaxDynamicSharedMemorySize,
                         (int)sizeof(SmemT));

    prep_giemb<<<(CC * VV * GG + 127) / 128, 128>>>(Wih0, embed);
    prep_wpk2<<<(CC * 288 * 96 + 127) / 128, 128>>>(Wih0, Wih_rest, Whh, W_h2e, W_ad);
    prep_bpk2<<<(CC * 288 + 127) / 128, 128>>>(Wih0, bih, bhh, b_h2e, b_ad);

    for (int c = 0; c < CC; c++) {
        qpre_kernel<<<(BB * RR * CL) / 32, 96>>>(c, x);
        rnn_kernel<<<BB, 576, sizeof(SmemT)>>>(c);
    }
    proj_kernel<<<(BB * CC * RR * CL) / 64, 256>>>(W_out, b_out, out);
}